// round 8
// baseline (speedup 1.0000x reference)
#include <cuda_runtime.h>

#define NF     10
#define VFIELD 10000
#define VTOT   100000
#define NBATCH 16384
#define NPAIR  45

// Pair table: code = i | (j << 8), all (i<j) pairs for F=10, padded to 48.
__constant__ int c_pairs[48] = {
    0x0100, 0x0200, 0x0300, 0x0400, 0x0500, 0x0600, 0x0700, 0x0800, 0x0900,
    0x0201, 0x0301, 0x0401, 0x0501, 0x0601, 0x0701, 0x0801, 0x0901,
    0x0302, 0x0402, 0x0502, 0x0602, 0x0702, 0x0802, 0x0902,
    0x0403, 0x0503, 0x0603, 0x0703, 0x0803, 0x0903,
    0x0504, 0x0604, 0x0704, 0x0804, 0x0904,
    0x0605, 0x0705, 0x0805, 0x0905,
    0x0706, 0x0806, 0x0906,
    0x0807, 0x0907,
    0x0908,
    0x0100, 0x0100, 0x0100   // padding (predicated out)
};

// One warp per batch element; one 4-lane quad per pair slot (8 slots/pass,
// 6 passes = 48 slots covering 45 pairs). Quad lanes cover one 64B embedding
// row contiguously, so each warp-wide LDG.128 touches only 8 distinct lines.
//
// This kernel is pinned to the LTS service-bandwidth roofline: 94.4MB of
// gathered row traffic per launch / ~6300 B/cyc chip cap ~= 13.7us. All
// scheduling/caching/path variants (R2-R7) measured identical within noise,
// so this restores the simplest form (best observed: 13.2us) with 512-thread
// blocks for minimal launch/wave overhead.
__global__ void __launch_bounds__(512) ffm_kernel(
    const int*   __restrict__ x,        // (B, F) int32
    const float* __restrict__ emb,      // (F, V, D) float32
    const float* __restrict__ lw,       // (V, 1) float32
    const float* __restrict__ bias,     // (1,)   float32
    float*       __restrict__ out)      // (B,)   float32
{
    const int warp = (blockIdx.x * blockDim.x + threadIdx.x) >> 5;
    const int lane = threadIdx.x & 31;

    const int q = lane >> 2;              // quad id 0..7 (pair slot)
    const unsigned sb = (lane & 3) << 4;  // byte slot within 64B row

    // offsets[f] == f * VFIELD by construction; hardcoded so idxv is one load.
    const int fld  = (lane < NF) ? lane : 0;
    const int idxv = x[warp * NF + fld] + fld * VFIELD;

    // Linear term: lanes 0..9 gather lin_weight; folded into the same reduce.
    float acc = (lane < NF) ? lw[idxv] : 0.0f;

    const char* base = (const char*)emb;

    #pragma unroll
    for (int t = 0; t < 6; t++) {
        const int  p     = t * 8 + q;
        const bool valid = (p < NPAIR);
        const int  pp    = c_pairs[valid ? p : 0];
        const int  i     = pp & 0xff;
        const int  j     = pp >> 8;
        const int idx_i = __shfl_sync(0xffffffffu, idxv, i);
        const int idx_j = __shfl_sync(0xffffffffu, idxv, j);
        if (valid) {
            // rows are 64B-aligned: byte offset = (f*VTOT + idx) * 64 (< 2^31)
            const float4 a = *(const float4*)(base + (((unsigned)(j * VTOT + idx_i)) << 6) + sb);
            const float4 b = *(const float4*)(base + (((unsigned)(i * VTOT + idx_j)) << 6) + sb);
            acc += a.x * b.x + a.y * b.y + a.z * b.z + a.w * b.w;
        }
    }

    // Full-warp butterfly reduce: pair partials + linear gathers.
    #pragma unroll
    for (int o = 16; o; o >>= 1)
        acc += __shfl_xor_sync(0xffffffffu, acc, o);

    if (lane == 0)
        out[warp] = acc + bias[0];
}

extern "C" void kernel_launch(void* const* d_in, const int* in_sizes, int n_in,
                              void* d_out, int out_size)
{
    const int*   x    = (const int*)  d_in[0];
    const float* emb  = (const float*)d_in[2];
    const float* lw   = (const float*)d_in[3];
    const float* bias = (const float*)d_in[4];
    float*       out  = (float*)d_out;

    // 16384 warps, 16 warps (512 threads) per block -> 1024 blocks
    ffm_kernel<<<NBATCH / 16, 512>>>(x, emb, lw, bias, out);
}

// round 9
// speedup vs baseline: 1.0312x; 1.0312x over previous
#include <cuda_runtime.h>

#define NF     10
#define VFIELD 10000
#define VTOT   100000
#define NBATCH 16384
#define NPAIR  45

// Pair table: code = i | (j << 8), all (i<j) pairs for F=10, padded to 48.
__constant__ int c_pairs[48] = {
    0x0100, 0x0200, 0x0300, 0x0400, 0x0500, 0x0600, 0x0700, 0x0800, 0x0900,
    0x0201, 0x0301, 0x0401, 0x0501, 0x0601, 0x0701, 0x0801, 0x0901,
    0x0302, 0x0402, 0x0502, 0x0602, 0x0702, 0x0802, 0x0902,
    0x0403, 0x0503, 0x0603, 0x0703, 0x0803, 0x0903,
    0x0504, 0x0604, 0x0704, 0x0804, 0x0904,
    0x0605, 0x0705, 0x0805, 0x0905,
    0x0706, 0x0806, 0x0906,
    0x0807, 0x0907,
    0x0908,
    0x0100, 0x0100, 0x0100   // padding (predicated out)
};

#define SPW 2  // samples per warp: grid shrinks to ONE wave (1024 blocks <= ~1036 concurrent)

// One warp per SPW batch elements; one 4-lane quad per pair slot (8 slots/
// pass, 6 passes = 48 slots covering 45 pairs). Quad lanes cover one 64B
// embedding row contiguously, so each warp-wide LDG.128 touches only 8
// distinct 128B lines. Single-wave grid removes the inter-wave transition
// and the second wave's latency ramp.
__global__ void __launch_bounds__(256) ffm_kernel(
    const int*   __restrict__ x,        // (B, F) int32
    const float* __restrict__ emb,      // (F, V, D) float32
    const float* __restrict__ lw,       // (V, 1) float32
    const float* __restrict__ bias,     // (1,)   float32
    float*       __restrict__ out)      // (B,)   float32
{
    const int warp0 = (blockIdx.x * blockDim.x + threadIdx.x) >> 5;
    const int lane  = threadIdx.x & 31;

    const int q = lane >> 2;              // quad id 0..7 (pair slot)
    const unsigned sb = (lane & 3) << 4;  // byte slot within 64B row
    const int fld = (lane < NF) ? lane : 0;
    const char* base = (const char*)emb;
    const float bs = bias[0];

    #pragma unroll
    for (int sidx = 0; sidx < SPW; sidx++) {
        const int b = warp0 + sidx * (NBATCH / SPW);

        // offsets[f] == f * VFIELD by construction; hardcoded -> one load.
        const int idxv = x[b * NF + fld] + fld * VFIELD;

        // Linear term: lanes 0..9 gather lin_weight; folded into the reduce.
        float acc = (lane < NF) ? lw[idxv] : 0.0f;

        #pragma unroll
        for (int t = 0; t < 6; t++) {
            const int  p     = t * 8 + q;
            const bool valid = (p < NPAIR);
            const int  pp    = c_pairs[valid ? p : 0];
            const int  i     = pp & 0xff;
            const int  j     = pp >> 8;
            const int idx_i = __shfl_sync(0xffffffffu, idxv, i);
            const int idx_j = __shfl_sync(0xffffffffu, idxv, j);
            if (valid) {
                // rows are 64B-aligned: byte offset = (f*VTOT + idx)*64 (< 2^31)
                const float4 a = *(const float4*)(base + (((unsigned)(j * VTOT + idx_i)) << 6) + sb);
                const float4 v = *(const float4*)(base + (((unsigned)(i * VTOT + idx_j)) << 6) + sb);
                acc += a.x * v.x + a.y * v.y + a.z * v.z + a.w * v.w;
            }
        }

        // Full-warp butterfly reduce: pair partials + linear gathers.
        #pragma unroll
        for (int o = 16; o; o >>= 1)
            acc += __shfl_xor_sync(0xffffffffu, acc, o);

        if (lane == 0)
            out[b] = acc + bs;
    }
}

extern "C" void kernel_launch(void* const* d_in, const int* in_sizes, int n_in,
                              void* d_out, int out_size)
{
    const int*   x    = (const int*)  d_in[0];
    const float* emb  = (const float*)d_in[2];
    const float* lw   = (const float*)d_in[3];
    const float* bias = (const float*)d_in[4];
    float*       out  = (float*)d_out;

    // 8192 warps x 2 samples; 8 warps/block -> 1024 blocks (single wave)
    ffm_kernel<<<NBATCH / (8 * SPW), 256>>>(x, emb, lw, bias, out);
}